// round 9
// baseline (speedup 1.0000x reference)
#include <cuda_runtime.h>
#include <cuda_fp16.h>
#include <cstdint>

// Problem constants
#define BT   192          // B*T
#define NN   512          // nodes
#define EE   4096         // edges
#define DD   128          // in dim
#define HH   4            // heads
#define DH   32           // per-head dim
#define OD   128          // out dim = HH*DH
#define NEG_SLOPE 0.2f
#define LN_EPS 1e-5f

// -------------------- device scratch (no allocations allowed) --------------------
__device__ __half g_hh[(size_t)BT * NN * OD];   // projected features in fp16, 25 MB
__device__ float g_ssrc[BT * NN * HH];          // per-node src attention scores
__device__ float g_sdst[BT * NN * HH];          // per-node dst attention scores
__device__ int   g_src[EE];                     // decoded src indices
__device__ int   g_eid[EE];                     // CSR edge ids (sorted per bucket)
__device__ int   g_off[NN + 1];                 // CSR offsets by dst

// ==================== Kernel 1: build dst-CSR (single block, all-smem) ====================
__global__ void build_csr_kernel(const int* __restrict__ ei)
{
    __shared__ int s_cnt[NN];      // 2 KB
    __shared__ int s_scan[NN];     // 2 KB
    __shared__ int s_cur[NN];      // 2 KB
    __shared__ int s_eid[EE];      // 16 KB — buckets live here, not in global
    __shared__ int s_mode;

    const int tid = threadIdx.x;  // 512 threads
    const unsigned FULL = 0xffffffffu;

    // Parallel int64-vs-int32 detection: warp 0 samples 64 odd 32-bit words of
    // the first row. For int64 (little-endian, values < 512) all high words are 0.
    if (tid < 32) {
        int v = ei[2 * tid + 1] | ei[2 * (tid + 32) + 1];
        unsigned b = __ballot_sync(FULL, v != 0);
        if (tid == 0) s_mode = (b == 0) ? 1 : 0;
    }
    s_cnt[tid] = 0;
    __syncthreads();
    const int mode = s_mode;

    // decode src + dst (dst kept in registers), count dst
    int dloc[EE / NN];             // 8 edges per thread
#pragma unroll
    for (int k = 0; k < EE / NN; k++) {
        int e = tid + k * NN;
        int s, d;
        if (mode) { s = ei[2 * e]; d = ei[2 * (EE + e)]; }
        else      { s = ei[e];     d = ei[EE + e]; }
        g_src[e] = s;
        dloc[k] = d;
        atomicAdd(&s_cnt[d], 1);
    }
    __syncthreads();

    // inclusive scan (Hillis-Steele) over 512 counts
    int v = s_cnt[tid];
    s_scan[tid] = v;
    __syncthreads();
#pragma unroll
    for (int d = 1; d < NN; d <<= 1) {
        int t = (tid >= d) ? s_scan[tid - d] : 0;
        __syncthreads();
        s_scan[tid] += t;
        __syncthreads();
    }
    g_off[tid + 1] = s_scan[tid];
    if (tid == 0) g_off[0] = 0;
    s_cur[tid] = s_scan[tid] - s_cnt[tid];   // exclusive prefix
    __syncthreads();

    // fill buckets in smem (order nondeterministic here)
#pragma unroll
    for (int k = 0; k < EE / NN; k++) {
        int e = tid + k * NN;
        int pos = atomicAdd(&s_cur[dloc[k]], 1);
        s_eid[pos] = e;
    }
    __syncthreads();

    // deterministic order: insertion sort each bucket by edge id (smem-resident)
    {
        int b0 = s_scan[tid] - s_cnt[tid];
        int b1 = s_scan[tid];
        for (int i = b0 + 1; i < b1; i++) {
            int key = s_eid[i];
            int j = i - 1;
            while (j >= b0 && s_eid[j] > key) { s_eid[j + 1] = s_eid[j]; j--; }
            s_eid[j + 1] = key;
        }
    }
    __syncthreads();

    // coalesced writeback
#pragma unroll
    for (int k = 0; k < EE / NN; k++) {
        int i = tid + k * NN;
        g_eid[i] = s_eid[i];
    }
}

// ==================== Kernel 2: projection GEMM (A-split tf32) + scores ====================
// A is split hi/lo in registers (exact to ~21 mantissa bits); W is single tf32
// staged in smem (one-sided truncation, rel err <= 2^-11 << 1e-3 tolerance).
// h written to global as fp16 (only the aggregation gathers read it; scores
// are computed here from the exact fp32 accumulators).

__device__ __forceinline__ unsigned f2tf(float f)
{
    unsigned r;
    asm("cvt.rna.tf32.f32 %0, %1;" : "=r"(r) : "f"(f));
    return r;
}

__device__ __forceinline__ void mma8(float* c, const unsigned* a, unsigned b0, unsigned b1)
{
    asm volatile(
        "mma.sync.aligned.m16n8k8.row.col.f32.tf32.tf32.f32 "
        "{%0,%1,%2,%3},{%4,%5,%6,%7},{%8,%9},{%0,%1,%2,%3};"
        : "+f"(c[0]), "+f"(c[1]), "+f"(c[2]), "+f"(c[3])
        : "r"(a[0]), "r"(a[1]), "r"(a[2]), "r"(a[3]), "r"(b0), "r"(b1));
}

#define WSTRIDE 136        // 128 + 8 pad -> conflict-free B loads
#define KTILE   64         // K rows of W staged per phase (2 phases)

__global__ void __launch_bounds__(512)
gemm_proj_kernel(const float* __restrict__ x, const float* __restrict__ W,
                 const float* __restrict__ att_src, const float* __restrict__ att_dst)
{
    __shared__ unsigned Wb[KTILE * WSTRIDE];    // tf32 W K-slice (34.8 KB)

    const int tid = threadIdx.x;             // 512 threads, 16 warps
    const int warp = tid >> 5;
    const int lane = tid & 31;
    const int g = lane >> 2;                 // groupID (rows / n-cols)
    const int tg = lane & 3;                 // thread-in-group (k / col pairs)

    const int rowbase = blockIdx.x * 256 + warp * 16;
    const int row0 = rowbase + g;
    const int row1 = row0 + 8;

    float acc[16][4];
#pragma unroll
    for (int nt = 0; nt < 16; nt++) {
        acc[nt][0] = acc[nt][1] = acc[nt][2] = acc[nt][3] = 0.f;
    }

    const float* x0 = x + (size_t)row0 * DD;
    const float* x1 = x + (size_t)row1 * DD;

    float af[4];
    af[0] = x0[tg]; af[1] = x1[tg]; af[2] = x0[tg + 4]; af[3] = x1[tg + 4];

    for (int p = 0; p < DD / KTILE; p++) {
        // stage K-slice of W (rows p*KTILE ..), single tf32
        __syncthreads();   // previous phase's smem reads complete
        for (int i = tid; i < KTILE * 128; i += 512) {
            int r = i >> 7, c = i & 127;
            Wb[r * WSTRIDE + c] = f2tf(W[(p * KTILE + r) * 128 + c]);
        }
        __syncthreads();

#pragma unroll
        for (int kt = 0; kt < KTILE / 8; kt++) {
            float ac[4] = { af[0], af[1], af[2], af[3] };
            int kglob = p * KTILE + kt * 8;
            if (kglob + 8 < DD) {  // prefetch next A fragment from global
                int c = kglob + 8 + tg;
                af[0] = x0[c]; af[1] = x1[c]; af[2] = x0[c + 4]; af[3] = x1[c + 4];
            }
            unsigned ab[4], al[4];
#pragma unroll
            for (int i = 0; i < 4; i++) {
                ab[i] = f2tf(ac[i]);
                al[i] = f2tf(ac[i] - __uint_as_float(ab[i]));
            }
            const unsigned* wb0 = &Wb[(kt * 8 + tg) * WSTRIDE];
            const unsigned* wb1 = &Wb[(kt * 8 + tg + 4) * WSTRIDE];
#pragma unroll
            for (int nt = 0; nt < 16; nt++) {
                unsigned bb0 = wb0[nt * 8 + g], bb1 = wb1[nt * 8 + g];
                mma8(acc[nt], ab, bb0, bb1);   // a_hi * w
                mma8(acc[nt], al, bb0, bb1);   // a_lo * w
            }
        }
    }

    // ---- epilogue: write h as fp16 ----
#pragma unroll
    for (int nt = 0; nt < 16; nt++) {
        __half2 h0 = __floats2half2_rn(acc[nt][0], acc[nt][1]);
        __half2 h1 = __floats2half2_rn(acc[nt][2], acc[nt][3]);
        *(__half2*)&g_hh[(size_t)row0 * OD + nt * 8 + tg * 2] = h0;
        *(__half2*)&g_hh[(size_t)row1 * OD + nt * 8 + tg * 2] = h1;
    }

    // ---- epilogue: fused attention scores s_src / s_dst (exact fp32) ----
#pragma unroll
    for (int h = 0; h < HH; h++) {
        float ps0 = 0.f, pd0 = 0.f, ps1 = 0.f, pd1 = 0.f;
#pragma unroll
        for (int q = 0; q < 4; q++) {
            int nt = 4 * h + q;
            int c0 = nt * 8 + tg * 2;
            float a0 = att_src[c0], a1 = att_src[c0 + 1];
            float d0 = att_dst[c0], d1 = att_dst[c0 + 1];
            ps0 += acc[nt][0] * a0 + acc[nt][1] * a1;
            pd0 += acc[nt][0] * d0 + acc[nt][1] * d1;
            ps1 += acc[nt][2] * a0 + acc[nt][3] * a1;
            pd1 += acc[nt][2] * d0 + acc[nt][3] * d1;
        }
#pragma unroll
        for (int off = 1; off <= 2; off <<= 1) {
            ps0 += __shfl_xor_sync(0xffffffffu, ps0, off);
            pd0 += __shfl_xor_sync(0xffffffffu, pd0, off);
            ps1 += __shfl_xor_sync(0xffffffffu, ps1, off);
            pd1 += __shfl_xor_sync(0xffffffffu, pd1, off);
        }
        if (tg == 0) {
            g_ssrc[row0 * HH + h] = ps0;
            g_sdst[row0 * HH + h] = pd0;
            g_ssrc[row1 * HH + h] = ps1;
            g_sdst[row1 * HH + h] = pd1;
        }
    }
}

// ==================== Kernel 3: softmax-aggregate + LN + ELU ====================
// One warp per (bt, dst). Lane l owns dims (2l, 2l+1) of each 64-dim head-pair:
//   group A = cols [0,64)   (heads 0,1: lanes 0-15 -> head 0, lanes 16-31 -> head 1)
//   group B = cols [64,128) (heads 2,3 likewise)
// fp16 gathers: 2x LDG.32 per edge (half2), 128 B coalesced per group.
// Guard-free batches: lanes >= n carry p == 0 exactly and src == 0 is safe.

__device__ __forceinline__ float leaky(float x) { return x > 0.f ? x : NEG_SLOPE * x; }

__global__ void __launch_bounds__(256)
agg_ln_kernel(const float* __restrict__ ew, const float* __restrict__ bias,
              const float* __restrict__ gamma, const float* __restrict__ beta,
              float* __restrict__ out)
{
    const int warp = threadIdx.x >> 5;
    const int lane = threadIdx.x & 31;
    const int wid = blockIdx.x * 8 + warp;       // global (bt,dst) id
    const int bt = wid >> 9;
    const int dst = wid & (NN - 1);
    const unsigned FULL = 0xffffffffu;
    const bool lowhead = (lane < 16);            // head 0/2 vs head 1/3

    const int nrow = bt * NN + dst;
    const float4 sd = *(const float4*)&g_sdst[nrow * HH];
    // half2 view of this bt's h slab; lane l reads index [src*64 + g*32 + lane]
    const __half2* hb = (const __half2*)(g_hh + (size_t)bt * NN * OD);

    const int j0 = g_off[dst];
    const int j1 = g_off[dst + 1];

    // running softmax state per head (head-uniform across lanes)
    float m0 = -1e30f, m1 = -1e30f, m2 = -1e30f, m3 = -1e30f;
    float dn0 = 0.f, dn1 = 0.f, dn2 = 0.f, dn3 = 0.f;
    // per-lane accumulators: 2 dims x 2 groups
    float aa0 = 0.f, aa1 = 0.f, ab0 = 0.f, ab1 = 0.f;

    for (int base = j0; base < j1; base += 32) {
        int n = j1 - base; if (n > 32) n = 32;

        // each lane owns one edge of this chunk
        int src = 0; float e0 = -1e30f, e1 = -1e30f, e2 = -1e30f, e3 = -1e30f;
        if (lane < n) {
            int eid = g_eid[base + lane];
            src = g_src[eid];
            float w = ew[eid];
            float4 ss = *(const float4*)&g_ssrc[(bt * NN + src) * HH];
            e0 = leaky(ss.x + sd.x) * w;
            e1 = leaky(ss.y + sd.y) * w;
            e2 = leaky(ss.z + sd.z) * w;
            e3 = leaky(ss.w + sd.w) * w;
        }

        // chunk max per head (warp reduce)
        float c0 = e0, c1 = e1, c2 = e2, c3 = e3;
#pragma unroll
        for (int off = 16; off >= 1; off >>= 1) {
            c0 = fmaxf(c0, __shfl_xor_sync(FULL, c0, off));
            c1 = fmaxf(c1, __shfl_xor_sync(FULL, c1, off));
            c2 = fmaxf(c2, __shfl_xor_sync(FULL, c2, off));
            c3 = fmaxf(c3, __shfl_xor_sync(FULL, c3, off));
        }
        // per-lane unnormalized probs (masked lanes -> underflow to exactly 0)
        float p0 = __expf(e0 - c0), p1 = __expf(e1 - c1);
        float p2 = __expf(e2 - c2), p3 = __expf(e3 - c3);
        // chunk denom per head
        float q0 = p0, q1 = p1, q2 = p2, q3 = p3;
#pragma unroll
        for (int off = 16; off >= 1; off >>= 1) {
            q0 += __shfl_xor_sync(FULL, q0, off);
            q1 += __shfl_xor_sync(FULL, q1, off);
            q2 += __shfl_xor_sync(FULL, q2, off);
            q3 += __shfl_xor_sync(FULL, q3, off);
        }

        // chunk aggregation: guard-free batches of 8 edges, 16 LDG.32 in flight.
        float ca0 = 0.f, ca1 = 0.f, cb0 = 0.f, cb1 = 0.f;
        for (int i0 = 0; i0 < n; i0 += 8) {
            __half2 hv[8][2];
#pragma unroll
            for (int j = 0; j < 8; j++) {
                int s = __shfl_sync(FULL, src, i0 + j);
                const __half2* p = hb + (size_t)s * 64 + lane;
                hv[j][0] = p[0];    // group A: dims 2l,2l+1
                hv[j][1] = p[32];   // group B: dims 64+2l,65+2l
            }
#pragma unroll
            for (int j = 0; j < 8; j++) {
                float pi0 = __shfl_sync(FULL, p0, i0 + j);
                float pi1 = __shfl_sync(FULL, p1, i0 + j);
                float pi2 = __shfl_sync(FULL, p2, i0 + j);
                float pi3 = __shfl_sync(FULL, p3, i0 + j);
                float pa = lowhead ? pi0 : pi1;
                float pb = lowhead ? pi2 : pi3;
                float2 fa = __half22float2(hv[j][0]);
                float2 fb = __half22float2(hv[j][1]);
                ca0 += pa * fa.x; ca1 += pa * fa.y;
                cb0 += pb * fb.x; cb1 += pb * fb.y;
            }
        }

        // merge chunk into running state (online softmax)
        float nm0 = fmaxf(m0, c0), nm1 = fmaxf(m1, c1);
        float nm2 = fmaxf(m2, c2), nm3 = fmaxf(m3, c3);
        float so0 = __expf(m0 - nm0), sn0 = __expf(c0 - nm0);
        float so1 = __expf(m1 - nm1), sn1 = __expf(c1 - nm1);
        float so2 = __expf(m2 - nm2), sn2 = __expf(c2 - nm2);
        float so3 = __expf(m3 - nm3), sn3 = __expf(c3 - nm3);
        dn0 = dn0 * so0 + q0 * sn0; m0 = nm0;
        dn1 = dn1 * so1 + q1 * sn1; m1 = nm1;
        dn2 = dn2 * so2 + q2 * sn2; m2 = nm2;
        dn3 = dn3 * so3 + q3 * sn3; m3 = nm3;
        float soa = lowhead ? so0 : so1, sna = lowhead ? sn0 : sn1;
        float sob = lowhead ? so2 : so3, snb = lowhead ? sn2 : sn3;
        aa0 = aa0 * soa + ca0 * sna; aa1 = aa1 * soa + ca1 * sna;
        ab0 = ab0 * sob + cb0 * snb; ab1 = ab1 * sob + cb1 * snb;
    }

    const float dna = (lowhead ? dn0 : dn1) + 1e-16f;
    const float dnb = (lowhead ? dn2 : dn3) + 1e-16f;
    const float2 ba = *(const float2*)&bias[2 * lane];
    const float2 bb = *(const float2*)&bias[64 + 2 * lane];
    float va0 = aa0 / dna + ba.x;
    float va1 = aa1 / dna + ba.y;
    float vb0 = ab0 / dnb + bb.x;
    float vb1 = ab1 / dnb + bb.y;

    // LayerNorm over the 128 values held by this warp
    float s = va0 + va1 + vb0 + vb1;
    float sq = va0 * va0 + va1 * va1 + vb0 * vb0 + vb1 * vb1;
#pragma unroll
    for (int off = 16; off >= 1; off >>= 1) {
        s += __shfl_xor_sync(FULL, s, off);
        sq += __shfl_xor_sync(FULL, sq, off);
    }
    float mu = s * (1.0f / OD);
    float var = sq * (1.0f / OD) - mu * mu;
    float rs = rsqrtf(var + LN_EPS);

    const float2 ga = *(const float2*)&gamma[2 * lane];
    const float2 gb = *(const float2*)&gamma[64 + 2 * lane];
    const float2 ea = *(const float2*)&beta[2 * lane];
    const float2 eb = *(const float2*)&beta[64 + 2 * lane];

    float y0 = (va0 - mu) * rs * ga.x + ea.x;
    float y1 = (va1 - mu) * rs * ga.y + ea.y;
    float y2 = (vb0 - mu) * rs * gb.x + eb.x;
    float y3 = (vb1 - mu) * rs * gb.y + eb.y;
    y0 = y0 > 0.f ? y0 : expm1f(y0);
    y1 = y1 > 0.f ? y1 : expm1f(y1);
    y2 = y2 > 0.f ? y2 : expm1f(y2);
    y3 = y3 > 0.f ? y3 : expm1f(y3);

    float* orow = out + (size_t)wid * OD;
    *(float2*)&orow[2 * lane] = make_float2(y0, y1);
    *(float2*)&orow[64 + 2 * lane] = make_float2(y2, y3);
}

// ==================== launcher ====================
extern "C" void kernel_launch(void* const* d_in, const int* in_sizes, int n_in,
                              void* d_out, int out_size)
{
    const float* x     = (const float*)d_in[0];
    const int*   ei    = (const int*)  d_in[1];   // int32 or int64 (auto-detected)
    const float* ew    = (const float*)d_in[2];
    const float* W     = (const float*)d_in[3];
    const float* asrc  = (const float*)d_in[4];
    const float* adst  = (const float*)d_in[5];
    const float* bias  = (const float*)d_in[6];
    const float* gamma = (const float*)d_in[7];
    const float* beta  = (const float*)d_in[8];
    float* out = (float*)d_out;

    build_csr_kernel<<<1, NN>>>(ei);
    gemm_proj_kernel<<<(BT * NN) / 256, 512>>>(x, W, asrc, adst);
    agg_ln_kernel<<<(BT * NN) / 8, 256>>>(ew, bias, gamma, beta, out);
}

// round 10
// speedup vs baseline: 1.1535x; 1.1535x over previous
#include <cuda_runtime.h>
#include <cuda_bf16.h>
#include <cstdint>

// Problem constants
#define BT   192          // B*T
#define NN   512          // nodes
#define EE   4096         // edges
#define DD   128          // in dim
#define HH   4            // heads
#define DH   32           // per-head dim
#define OD   128          // out dim = HH*DH
#define NEG_SLOPE 0.2f
#define LN_EPS 1e-5f

// -------------------- device scratch (no allocations allowed) --------------------
__device__ float g_h[(size_t)BT * NN * OD];     // projected features, 50.3 MB
__device__ float g_ssrc[BT * NN * HH];          // per-node src attention scores
__device__ float g_sdst[BT * NN * HH];          // per-node dst attention scores
__device__ int   g_src[EE];                     // decoded src indices
__device__ int   g_eid[EE];                     // CSR edge ids (sorted per bucket)
__device__ int   g_off[NN + 1];                 // CSR offsets by dst

// ==================== Kernel 1: build dst-CSR (single block, all-smem) ====================
__global__ void build_csr_kernel(const int* __restrict__ ei)
{
    __shared__ int s_cnt[NN];      // 2 KB
    __shared__ int s_scan[NN];     // 2 KB
    __shared__ int s_cur[NN];      // 2 KB
    __shared__ int s_eid[EE];      // 16 KB — buckets live here, not in global
    __shared__ int s_mode;

    const int tid = threadIdx.x;  // 512 threads
    const unsigned FULL = 0xffffffffu;

    // Parallel int64-vs-int32 detection: warp 0 samples 64 odd 32-bit words of
    // the first row. For int64 (little-endian, values < 512) all high words are 0.
    if (tid < 32) {
        int v = ei[2 * tid + 1] | ei[2 * (tid + 32) + 1];
        unsigned b = __ballot_sync(FULL, v != 0);
        if (tid == 0) s_mode = (b == 0) ? 1 : 0;
    }
    s_cnt[tid] = 0;
    __syncthreads();
    const int mode = s_mode;

    // decode src + dst (dst kept in registers), count dst
    int dloc[EE / NN];             // 8 edges per thread
#pragma unroll
    for (int k = 0; k < EE / NN; k++) {
        int e = tid + k * NN;
        int s, d;
        if (mode) { s = ei[2 * e]; d = ei[2 * (EE + e)]; }
        else      { s = ei[e];     d = ei[EE + e]; }
        g_src[e] = s;
        dloc[k] = d;
        atomicAdd(&s_cnt[d], 1);
    }
    __syncthreads();

    // inclusive scan (Hillis-Steele) over 512 counts
    int v = s_cnt[tid];
    s_scan[tid] = v;
    __syncthreads();
#pragma unroll
    for (int d = 1; d < NN; d <<= 1) {
        int t = (tid >= d) ? s_scan[tid - d] : 0;
        __syncthreads();
        s_scan[tid] += t;
        __syncthreads();
    }
    g_off[tid + 1] = s_scan[tid];
    if (tid == 0) g_off[0] = 0;
    s_cur[tid] = s_scan[tid] - s_cnt[tid];   // exclusive prefix
    __syncthreads();

    // fill buckets in smem (order nondeterministic here)
#pragma unroll
    for (int k = 0; k < EE / NN; k++) {
        int e = tid + k * NN;
        int pos = atomicAdd(&s_cur[dloc[k]], 1);
        s_eid[pos] = e;
    }
    __syncthreads();

    // deterministic order: insertion sort each bucket by edge id (smem-resident)
    {
        int b0 = s_scan[tid] - s_cnt[tid];
        int b1 = s_scan[tid];
        for (int i = b0 + 1; i < b1; i++) {
            int key = s_eid[i];
            int j = i - 1;
            while (j >= b0 && s_eid[j] > key) { s_eid[j + 1] = s_eid[j]; j--; }
            s_eid[j + 1] = key;
        }
    }
    __syncthreads();

    // coalesced writeback
#pragma unroll
    for (int k = 0; k < EE / NN; k++) {
        int i = tid + k * NN;
        g_eid[i] = s_eid[i];
    }
}

// ==================== Kernel 2: projection GEMM (A-split tf32) + scores ====================
// Column-split warps for occupancy: block = 256 threads = 8 warps covering a
// 64-row x 128-col output tile; each warp owns 16 rows x 64 cols (acc = 32
// regs -> ~70 regs/thread -> ~3 CTAs/SM = 24 warps/SM, vs 1 CTA/16 warps
// before). A is split hi/lo in registers (exact); W single tf32 in smem
// (one-sided truncation, rel err <= 2^-11).

__device__ __forceinline__ unsigned f2tf(float f)
{
    unsigned r;
    asm("cvt.rna.tf32.f32 %0, %1;" : "=r"(r) : "f"(f));
    return r;
}

__device__ __forceinline__ void mma8(float* c, const unsigned* a, unsigned b0, unsigned b1)
{
    asm volatile(
        "mma.sync.aligned.m16n8k8.row.col.f32.tf32.tf32.f32 "
        "{%0,%1,%2,%3},{%4,%5,%6,%7},{%8,%9},{%0,%1,%2,%3};"
        : "+f"(c[0]), "+f"(c[1]), "+f"(c[2]), "+f"(c[3])
        : "r"(a[0]), "r"(a[1]), "r"(a[2]), "r"(a[3]), "r"(b0), "r"(b1));
}

#define WSTRIDE 136        // 128 + 8 pad -> conflict-free B loads
#define KTILE   64         // K rows of W staged per phase (2 phases)

__global__ void __launch_bounds__(256)
gemm_proj_kernel(const float* __restrict__ x, const float* __restrict__ W,
                 const float* __restrict__ att_src, const float* __restrict__ att_dst)
{
    __shared__ unsigned Wb[KTILE * WSTRIDE];    // tf32 W K-slice (34.8 KB)

    const int tid = threadIdx.x;             // 256 threads, 8 warps
    const int warp = tid >> 5;
    const int lane = tid & 31;
    const int rowg = warp >> 1;              // 0..3 row-group
    const int colg = warp & 1;               // 0..1 col-group (64 cols each)
    const int g = lane >> 2;                 // groupID (rows / n-cols)
    const int tg = lane & 3;                 // thread-in-group (k / col pairs)

    const int rowbase = blockIdx.x * 64 + rowg * 16;
    const int row0 = rowbase + g;
    const int row1 = row0 + 8;
    const int colbase = colg * 64;

    float acc[8][4];
#pragma unroll
    for (int nt = 0; nt < 8; nt++) {
        acc[nt][0] = acc[nt][1] = acc[nt][2] = acc[nt][3] = 0.f;
    }

    const float* x0 = x + (size_t)row0 * DD;
    const float* x1 = x + (size_t)row1 * DD;

    float af[4];
    af[0] = x0[tg]; af[1] = x1[tg]; af[2] = x0[tg + 4]; af[3] = x1[tg + 4];

    for (int p = 0; p < DD / KTILE; p++) {
        // stage K-slice of W (rows p*KTILE ..), single tf32, float4 loads
        __syncthreads();   // previous phase's smem reads complete
        for (int i = tid; i < KTILE * 32; i += 256) {
            int r = i >> 5, c4 = (i & 31) * 4;
            const float4 f = *(const float4*)&W[(p * KTILE + r) * 128 + c4];
            unsigned* wp = &Wb[r * WSTRIDE + c4];
            wp[0] = f2tf(f.x); wp[1] = f2tf(f.y);
            wp[2] = f2tf(f.z); wp[3] = f2tf(f.w);
        }
        __syncthreads();

#pragma unroll
        for (int kt = 0; kt < KTILE / 8; kt++) {
            float ac[4] = { af[0], af[1], af[2], af[3] };
            int kglob = p * KTILE + kt * 8;
            if (kglob + 8 < DD) {  // prefetch next A fragment from global
                int c = kglob + 8 + tg;
                af[0] = x0[c]; af[1] = x1[c]; af[2] = x0[c + 4]; af[3] = x1[c + 4];
            }
            unsigned ab[4], al[4];
#pragma unroll
            for (int i = 0; i < 4; i++) {
                ab[i] = f2tf(ac[i]);
                al[i] = f2tf(ac[i] - __uint_as_float(ab[i]));
            }
            const unsigned* wb0 = &Wb[(kt * 8 + tg) * WSTRIDE + colbase];
            const unsigned* wb1 = &Wb[(kt * 8 + tg + 4) * WSTRIDE + colbase];
#pragma unroll
            for (int nt = 0; nt < 8; nt++) {
                unsigned bb0 = wb0[nt * 8 + g], bb1 = wb1[nt * 8 + g];
                mma8(acc[nt], ab, bb0, bb1);   // a_hi * w
                mma8(acc[nt], al, bb0, bb1);   // a_lo * w
            }
        }
    }

    // ---- epilogue: write h (this warp's 64-col slice) ----
#pragma unroll
    for (int nt = 0; nt < 8; nt++) {
        int col = colbase + nt * 8 + tg * 2;
        float2 v0 = make_float2(acc[nt][0], acc[nt][1]);
        float2 v1 = make_float2(acc[nt][2], acc[nt][3]);
        *(float2*)&g_h[(size_t)row0 * OD + col] = v0;
        *(float2*)&g_h[(size_t)row1 * OD + col] = v1;
    }

    // ---- epilogue: fused attention scores for this warp's 2 heads ----
#pragma unroll
    for (int hh = 0; hh < 2; hh++) {
        const int head = colg * 2 + hh;
        float ps0 = 0.f, pd0 = 0.f, ps1 = 0.f, pd1 = 0.f;
#pragma unroll
        for (int q = 0; q < 4; q++) {
            int nt = 4 * hh + q;
            int c0 = colbase + nt * 8 + tg * 2;
            float a0 = att_src[c0], a1 = att_src[c0 + 1];
            float d0 = att_dst[c0], d1 = att_dst[c0 + 1];
            ps0 += acc[nt][0] * a0 + acc[nt][1] * a1;
            pd0 += acc[nt][0] * d0 + acc[nt][1] * d1;
            ps1 += acc[nt][2] * a0 + acc[nt][3] * a1;
            pd1 += acc[nt][2] * d0 + acc[nt][3] * d1;
        }
#pragma unroll
        for (int off = 1; off <= 2; off <<= 1) {
            ps0 += __shfl_xor_sync(0xffffffffu, ps0, off);
            pd0 += __shfl_xor_sync(0xffffffffu, pd0, off);
            ps1 += __shfl_xor_sync(0xffffffffu, ps1, off);
            pd1 += __shfl_xor_sync(0xffffffffu, pd1, off);
        }
        if (tg == 0) {
            g_ssrc[row0 * HH + head] = ps0;
            g_sdst[row0 * HH + head] = pd0;
            g_ssrc[row1 * HH + head] = ps1;
            g_sdst[row1 * HH + head] = pd1;
        }
    }
}

// ==================== Kernel 3: softmax-aggregate + LN + ELU ====================
// One warp per (bt, dst). 32 lanes = 32 per-head feature dims (coalesced gathers).
// Gathers batched 8 edges deep, GUARD-FREE: lanes >= n carry p == 0 exactly
// (exp(-1e30 - c) underflows to 0) and src == 0 is a safe address, so OOB batch
// elements contribute nothing. Indices i0+j are provably <= 31.

__device__ __forceinline__ float leaky(float x) { return x > 0.f ? x : NEG_SLOPE * x; }

__global__ void __launch_bounds__(256)
agg_ln_kernel(const float* __restrict__ ew, const float* __restrict__ bias,
              const float* __restrict__ gamma, const float* __restrict__ beta,
              float* __restrict__ out)
{
    const int warp = threadIdx.x >> 5;
    const int lane = threadIdx.x & 31;
    const int wid = blockIdx.x * 8 + warp;       // global (bt,dst) id
    const int bt = wid >> 9;
    const int dst = wid & (NN - 1);
    const unsigned FULL = 0xffffffffu;

    const int nrow = bt * NN + dst;
    const float4 sd = *(const float4*)&g_sdst[nrow * HH];
    const float* hb = g_h + (size_t)bt * NN * OD + lane;

    const int j0 = g_off[dst];
    const int j1 = g_off[dst + 1];

    // running softmax state per head
    float m0 = -1e30f, m1 = -1e30f, m2 = -1e30f, m3 = -1e30f;
    float dn0 = 0.f, dn1 = 0.f, dn2 = 0.f, dn3 = 0.f;
    float ac0 = 0.f, ac1 = 0.f, ac2 = 0.f, ac3 = 0.f;

    for (int base = j0; base < j1; base += 32) {
        int n = j1 - base; if (n > 32) n = 32;

        // each lane owns one edge of this chunk
        int src = 0; float e0 = -1e30f, e1 = -1e30f, e2 = -1e30f, e3 = -1e30f;
        if (lane < n) {
            int eid = g_eid[base + lane];
            src = g_src[eid];
            float w = ew[eid];
            float4 ss = *(const float4*)&g_ssrc[(bt * NN + src) * HH];
            e0 = leaky(ss.x + sd.x) * w;
            e1 = leaky(ss.y + sd.y) * w;
            e2 = leaky(ss.z + sd.z) * w;
            e3 = leaky(ss.w + sd.w) * w;
        }

        // chunk max per head (warp reduce)
        float c0 = e0, c1 = e1, c2 = e2, c3 = e3;
#pragma unroll
        for (int off = 16; off >= 1; off >>= 1) {
            c0 = fmaxf(c0, __shfl_xor_sync(FULL, c0, off));
            c1 = fmaxf(c1, __shfl_xor_sync(FULL, c1, off));
            c2 = fmaxf(c2, __shfl_xor_sync(FULL, c2, off));
            c3 = fmaxf(c3, __shfl_xor_sync(FULL, c3, off));
        }
        // per-lane unnormalized probs (masked lanes -> underflow to exactly 0)
        float p0 = __expf(e0 - c0), p1 = __expf(e1 - c1);
        float p2 = __expf(e2 - c2), p3 = __expf(e3 - c3);
        // chunk denom per head
        float q0 = p0, q1 = p1, q2 = p2, q3 = p3;
#pragma unroll
        for (int off = 16; off >= 1; off >>= 1) {
            q0 += __shfl_xor_sync(FULL, q0, off);
            q1 += __shfl_xor_sync(FULL, q1, off);
            q2 += __shfl_xor_sync(FULL, q2, off);
            q3 += __shfl_xor_sync(FULL, q3, off);
        }

        // chunk aggregation: gather h[src] rows in guard-free batches of 8 edges.
        // 32 independent loads issue back-to-back -> MLP=32, zero branches.
        float ca0 = 0.f, ca1 = 0.f, ca2 = 0.f, ca3 = 0.f;
        for (int i0 = 0; i0 < n; i0 += 8) {
            float hv[8][4];
#pragma unroll
            for (int j = 0; j < 8; j++) {
                int s = __shfl_sync(FULL, src, i0 + j);
                const float* p = hb + (size_t)s * OD;
                hv[j][0] = p[0];  hv[j][1] = p[32];
                hv[j][2] = p[64]; hv[j][3] = p[96];
            }
#pragma unroll
            for (int j = 0; j < 8; j++) {
                float pi0 = __shfl_sync(FULL, p0, i0 + j);
                float pi1 = __shfl_sync(FULL, p1, i0 + j);
                float pi2 = __shfl_sync(FULL, p2, i0 + j);
                float pi3 = __shfl_sync(FULL, p3, i0 + j);
                ca0 += pi0 * hv[j][0]; ca1 += pi1 * hv[j][1];
                ca2 += pi2 * hv[j][2]; ca3 += pi3 * hv[j][3];
            }
        }

        // merge chunk into running state (online softmax)
        float nm0 = fmaxf(m0, c0), nm1 = fmaxf(m1, c1);
        float nm2 = fmaxf(m2, c2), nm3 = fmaxf(m3, c3);
        float so0 = __expf(m0 - nm0), sn0 = __expf(c0 - nm0);
        float so1 = __expf(m1 - nm1), sn1 = __expf(c1 - nm1);
        float so2 = __expf(m2 - nm2), sn2 = __expf(c2 - nm2);
        float so3 = __expf(m3 - nm3), sn3 = __expf(c3 - nm3);
        dn0 = dn0 * so0 + q0 * sn0; ac0 = ac0 * so0 + ca0 * sn0; m0 = nm0;
        dn1 = dn1 * so1 + q1 * sn1; ac1 = ac1 * so1 + ca1 * sn1; m1 = nm1;
        dn2 = dn2 * so2 + q2 * sn2; ac2 = ac2 * so2 + ca2 * sn2; m2 = nm2;
        dn3 = dn3 * so3 + q3 * sn3; ac3 = ac3 * so3 + ca3 * sn3; m3 = nm3;
    }

    float v0 = ac0 / (dn0 + 1e-16f) + bias[0 * DH + lane];
    float v1 = ac1 / (dn1 + 1e-16f) + bias[1 * DH + lane];
    float v2 = ac2 / (dn2 + 1e-16f) + bias[2 * DH + lane];
    float v3 = ac3 / (dn3 + 1e-16f) + bias[3 * DH + lane];

    // LayerNorm over the 128 values held by this warp
    float s = v0 + v1 + v2 + v3;
    float sq = v0 * v0 + v1 * v1 + v2 * v2 + v3 * v3;
#pragma unroll
    for (int off = 16; off >= 1; off >>= 1) {
        s += __shfl_xor_sync(FULL, s, off);
        sq += __shfl_xor_sync(FULL, sq, off);
    }
    float mu = s * (1.0f / OD);
    float var = sq * (1.0f / OD) - mu * mu;
    float rs = rsqrtf(var + LN_EPS);

    float* orow = out + (size_t)wid * OD;
#pragma unroll
    for (int h = 0; h < HH; h++) {
        float v = (h == 0) ? v0 : (h == 1) ? v1 : (h == 2) ? v2 : v3;
        int col = h * DH + lane;
        float y = (v - mu) * rs * gamma[col] + beta[col];
        orow[col] = y > 0.f ? y : expm1f(y);
    }
}

// ==================== launcher ====================
extern "C" void kernel_launch(void* const* d_in, const int* in_sizes, int n_in,
                              void* d_out, int out_size)
{
    const float* x     = (const float*)d_in[0];
    const int*   ei    = (const int*)  d_in[1];   // int32 or int64 (auto-detected)
    const float* ew    = (const float*)d_in[2];
    const float* W     = (const float*)d_in[3];
    const float* asrc  = (const float*)d_in[4];
    const float* adst  = (const float*)d_in[5];
    const float* bias  = (const float*)d_in[6];
    const float* gamma = (const float*)d_in[7];
    const float* beta  = (const float*)d_in[8];
    float* out = (float*)d_out;

    build_csr_kernel<<<1, NN>>>(ei);
    gemm_proj_kernel<<<(BT * NN) / 64, 256>>>(x, W, asrc, adst);
    agg_ln_kernel<<<(BT * NN) / 8, 256>>>(ew, bias, gamma, beta, out);
}